// round 16
// baseline (speedup 1.0000x reference)
#include <cuda_runtime.h>
#include <math.h>

#define W  2048
#define H  2048
#define NIMG 16

#define STRIP_OUT 248            // output columns per warp strip (8/lane)
#define NSTRIPS   9              // ceil(2048/248)
#define ROWT      128            // output rows per warp job
#define NROWT     16             // 2048/128
#define WARPS_PER_BLOCK 4
#define NTHREADS (WARPS_PER_BLOCK * 32)
#define NJOBS (NIMG * NROWT * NSTRIPS)          // 2304
#define NBLOCKS (NJOBS / WARPS_PER_BLOCK)       // 576  -> single wave @ 4 blk/SM

#define NEGINF (-__int_as_float(0x7f800000))

__device__ __forceinline__ float fsqrt_fast(float x)
{
    float r;
    asm("sqrt.approx.f32 %0, %1;" : "=f"(r) : "f"(x));
    return r;
}

__device__ __forceinline__ float4 ld4(const float* __restrict__ im,
                                      int y, int c, bool ok)
{
    if (!((unsigned)y < (unsigned)H) || !ok) return make_float4(0.f, 0.f, 0.f, 0.f);
    return *reinterpret_cast<const float4*>(im + (size_t)y * W + c);
}

// Pipeline step at input row y = ybase + IY, 8 columns per lane.
// Byte-identical to the 105us R10 body.
#define BODY(IY, DO_SM, DO_E, DO_ST) do {                                        \
    const int y_ = ybase + (IY);                                                 \
    float cur[8];                                                                \
    cur[0]=nx1a.x; cur[1]=nx1a.y; cur[2]=nx1a.z; cur[3]=nx1a.w;                  \
    cur[4]=nx1b.x; cur[5]=nx1b.y; cur[6]=nx1b.z; cur[7]=nx1b.w;                  \
    nx1a = nx2a; nx1b = nx2b;                                                    \
    nx2a = ld4(im, y_ + 2, c0,     okA);                                         \
    nx2b = ld4(im, y_ + 2, c0 + 4, okB);                                         \
    float hc[8];                                                                 \
    {                                                                            \
        float inm1 = __shfl_up_sync(0xffffffffu, cur[7], 1);                     \
        float inp8 = __shfl_down_sync(0xffffffffu, cur[0], 1);                   \
        hc[0] = inm1 + 2.f*cur[0] + cur[1];                                      \
        _Pragma("unroll") for (int j = 1; j < 7; j++)                            \
            hc[j] = cur[j-1] + 2.f*cur[j] + cur[j+1];                            \
        hc[7] = cur[6] + 2.f*cur[7] + inp8;                                      \
    }                                                                            \
    if (DO_SM) {                                                                 \
        const bool rowok = ((unsigned)(y_ - 1) < (unsigned)H);                   \
        const float mskA = rowok ? cmulA : 0.f;                                  \
        const float mskB = rowok ? cmulB : 0.f;                                  \
        float smc[8];                                                            \
        _Pragma("unroll") for (int j = 0; j < 4; j++)                            \
            smc[j] = (hB[j] + 2.f*hA[j] + hc[j]) * mskA;                         \
        _Pragma("unroll") for (int j = 4; j < 8; j++)                            \
            smc[j] = (hB[j] + 2.f*hA[j] + hc[j]) * mskB;                         \
        if (DO_E) {                                                              \
            float vs[8], vd[8];                                                  \
            _Pragma("unroll") for (int j = 0; j < 8; j++) {                      \
                vs[j] = smB[j] + 2.f*smA[j] + smc[j];                            \
                vd[j] = smc[j] - smB[j];                                         \
            }                                                                    \
            float vsm1 = __shfl_up_sync(0xffffffffu, vs[7], 1);                  \
            float vsp8 = __shfl_down_sync(0xffffffffu, vs[0], 1);                \
            float vdm1 = __shfl_up_sync(0xffffffffu, vd[7], 1);                  \
            float vdp8 = __shfl_down_sync(0xffffffffu, vd[0], 1);                \
            float ec[8];                                                         \
            {                                                                    \
                float gx, gy;                                                    \
                gx = vs[1] - vsm1; gy = vdm1 + 2.f*vd[0] + vd[1];                \
                ec[0] = fsqrt_fast(gx*gx + gy*gy);                               \
                _Pragma("unroll") for (int j = 1; j < 7; j++) {                  \
                    gx = vs[j+1] - vs[j-1];                                      \
                    gy = vd[j-1] + 2.f*vd[j] + vd[j+1];                          \
                    ec[j] = fsqrt_fast(gx*gx + gy*gy);                           \
                }                                                                \
                gx = vsp8 - vs[6]; gy = vd[6] + 2.f*vd[7] + vdp8;                \
                ec[7] = fsqrt_fast(gx*gx + gy*gy);                               \
            }                                                                    \
            float el = __shfl_up_sync(0xffffffffu, ec[7], 1);                    \
            float er = __shfl_down_sync(0xffffffffu, ec[0], 1);                  \
            float mc[8];                                                         \
            mc[0] = fmaxf(fmaxf(el, ec[0]), ec[1]);                              \
            _Pragma("unroll") for (int j = 1; j < 7; j++)                        \
                mc[j] = fmaxf(fmaxf(ec[j-1], ec[j]), ec[j+1]);                   \
            mc[7] = fmaxf(fmaxf(ec[6], ec[7]), er);                              \
            if (DO_ST) {                                                         \
                const int yo_ = y_ - 3;                                          \
                float r[8];                                                      \
                if ((yo_ > 0) && (yo_ < H - 1)) {   /* warp-uniform branch */    \
                    _Pragma("unroll") for (int j = 0; j < 8; j++) {              \
                        float nm = fmaxf(fmaxf(mRB[j], mRA[j]), mc[j])           \
                                   + colmsk[j];                                  \
                        r[j] = (eA[j] < nm) ? 0.f : eA[j];                       \
                    }                                                            \
                } else {                                                         \
                    _Pragma("unroll") for (int j = 0; j < 8; j++)                \
                        r[j] = eA[j];                                            \
                }                                                                \
                if (storerA)                                                     \
                    *reinterpret_cast<float4*>(op + (size_t)yo_ * W + c0) =      \
                        make_float4(r[0], r[1], r[2], r[3]);                     \
                if (storerB)                                                     \
                    *reinterpret_cast<float4*>(op + (size_t)yo_ * W + c0 + 4) =  \
                        make_float4(r[4], r[5], r[6], r[7]);                     \
            }                                                                    \
            _Pragma("unroll") for (int j = 0; j < 8; j++) {                      \
                eA[j] = ec[j]; mRB[j] = mRA[j]; mRA[j] = mc[j];                  \
            }                                                                    \
        }                                                                        \
        _Pragma("unroll") for (int j = 0; j < 8; j++) {                          \
            smB[j] = smA[j]; smA[j] = smc[j];                                    \
        }                                                                        \
    }                                                                            \
    _Pragma("unroll") for (int j = 0; j < 8; j++) {                              \
        hB[j] = hA[j]; hA[j] = hc[j];                                            \
    }                                                                            \
} while (0)

__global__ __launch_bounds__(NTHREADS, 4)
void edge_kernel(const float* __restrict__ img, float* __restrict__ out)
{
    const int lane = threadIdx.x & 31;
    const int warp = threadIdx.x >> 5;
    const int job  = blockIdx.x * WARPS_PER_BLOCK + warp;

    const int strip = job % NSTRIPS;
    const int t     = job / NSTRIPS;
    const int rowt  = t % NROWT;
    const int n     = t / NROWT;

    const int cb = strip * STRIP_OUT - 4;   // loaded column base (mult of 4)
    const int c0 = cb + lane * 8;           // this lane's first column
    const int y0 = rowt * ROWT;
    const int ybase = y0 - 3;

    const float* im = img + (size_t)n * H * W;
    float*       op = out + (size_t)n * H * W;

    // per-float4-group validity (groups are 4-aligned; W % 4 == 0)
    const bool okA = (c0     >= 0) && (c0     < W);
    const bool okB = (c0 + 4 >= 0) && (c0 + 4 < W);
    const float cmulA = okA ? 0.0625f : 0.f;
    const float cmulB = okB ? 0.0625f : 0.f;

    // stores: warp outputs cols cb+4 .. cb+251
    const bool storerA = (lane > 0)  && okA;
    const bool storerB = (lane < 31) && okB;

    // 0 interior, -inf at global col borders (kills suppression there)
    float colmsk[8];
    #pragma unroll
    for (int j = 0; j < 8; j++)
        colmsk[j] = ((c0 + j > 0) && (c0 + j < W - 1)) ? 0.f : NEGINF;

    float hA[8], hB[8], smA[8], smB[8], eA[8], mRA[8], mRB[8];
    #pragma unroll
    for (int j = 0; j < 8; j++) {
        hA[j]=hB[j]=0.f; smA[j]=smB[j]=0.f; eA[j]=0.f; mRA[j]=mRB[j]=0.f;
    }

    // 2-deep row prefetch (4 independent float4 loads in flight)
    float4 nx1a = ld4(im, ybase,     c0,     okA);
    float4 nx1b = ld4(im, ybase,     c0 + 4, okB);
    float4 nx2a = ld4(im, ybase + 1, c0,     okA);
    float4 nx2b = ld4(im, ybase + 1, c0 + 4, okB);

    // ---- warmup: 8 specialized iterations (first store at iy = 6) ----
    BODY(0, false, false, false);
    BODY(1, false, false, false);
    BODY(2, true,  false, false);
    BODY(3, true,  false, false);
    BODY(4, true,  true,  false);
    BODY(5, true,  true,  false);
    BODY(6, true,  true,  true);
    BODY(7, true,  true,  true);

    // ---- steady: iy = 8 .. ROWT+5, 126 iters = 31 x 4 + 2 ----
    // Unroll-4 gives the scheduler a wider static window to front-batch the
    // four LDG.128 pairs of a group (higher MLP_p1); ring depth 2 divides 4,
    // so register renaming is unchanged vs the 2x loop.
    int base = 8;
    for (; base + 3 < ROWT + 6; base += 4) {
        BODY(base + 0, true, true, true);
        BODY(base + 1, true, true, true);
        BODY(base + 2, true, true, true);
        BODY(base + 3, true, true, true);
    }
    BODY(base + 0, true, true, true);
    BODY(base + 1, true, true, true);
}

extern "C" void kernel_launch(void* const* d_in, const int* in_sizes, int n_in,
                              void* d_out, int out_size)
{
    const float* img = (const float*)d_in[0];
    float* out = (float*)d_out;
    edge_kernel<<<NBLOCKS, NTHREADS>>>(img, out);
}

// round 17
// speedup vs baseline: 1.1725x; 1.1725x over previous
#include <cuda_runtime.h>
#include <math.h>

#define W  2048
#define H  2048
#define NIMG 16

#define STRIP_OUT 248            // output columns per warp strip (8/lane)
#define NSTRIPS   9              // ceil(2048/248)
#define ROWT      128            // output rows per warp job
#define NROWT     16             // 2048/128
#define WARPS_PER_BLOCK 4
#define NTHREADS (WARPS_PER_BLOCK * 32)
#define NJOBS (NIMG * NROWT * NSTRIPS)          // 2304
#define NBLOCKS (NJOBS / WARPS_PER_BLOCK)       // 576  -> single wave @ 4 blk/SM

#define NEGINF (-__int_as_float(0x7f800000))

__device__ __forceinline__ float fsqrt_fast(float x)
{
    float r;
    asm("sqrt.approx.f32 %0, %1;" : "=f"(r) : "f"(x));
    return r;
}

__device__ __forceinline__ float4 ld4(const float* __restrict__ im,
                                      int y, int c, bool ok)
{
    if (!((unsigned)y < (unsigned)H) || !ok) return make_float4(0.f, 0.f, 0.f, 0.f);
    return *reinterpret_cast<const float4*>(im + (size_t)y * W + c);
}

// Pipeline step at input row y = ybase + IY, 8 columns per lane.
#define BODY(IY, DO_SM, DO_E, DO_ST) do {                                        \
    const int y_ = ybase + (IY);                                                 \
    float cur[8];                                                                \
    cur[0]=nx1a.x; cur[1]=nx1a.y; cur[2]=nx1a.z; cur[3]=nx1a.w;                  \
    cur[4]=nx1b.x; cur[5]=nx1b.y; cur[6]=nx1b.z; cur[7]=nx1b.w;                  \
    nx1a = nx2a; nx1b = nx2b;                                                    \
    nx2a = ld4(im, y_ + 2, c0,     okA);                                         \
    nx2b = ld4(im, y_ + 2, c0 + 4, okB);                                         \
    float hc[8];                                                                 \
    {                                                                            \
        float inm1 = __shfl_up_sync(0xffffffffu, cur[7], 1);                     \
        float inp8 = __shfl_down_sync(0xffffffffu, cur[0], 1);                   \
        hc[0] = inm1 + 2.f*cur[0] + cur[1];                                      \
        _Pragma("unroll") for (int j = 1; j < 7; j++)                            \
            hc[j] = cur[j-1] + 2.f*cur[j] + cur[j+1];                            \
        hc[7] = cur[6] + 2.f*cur[7] + inp8;                                      \
    }                                                                            \
    if (DO_SM) {                                                                 \
        const bool rowok = ((unsigned)(y_ - 1) < (unsigned)H);                   \
        const float mskA = rowok ? cmulA : 0.f;                                  \
        const float mskB = rowok ? cmulB : 0.f;                                  \
        float smc[8];                                                            \
        _Pragma("unroll") for (int j = 0; j < 4; j++)                            \
            smc[j] = (hB[j] + 2.f*hA[j] + hc[j]) * mskA;                         \
        _Pragma("unroll") for (int j = 4; j < 8; j++)                            \
            smc[j] = (hB[j] + 2.f*hA[j] + hc[j]) * mskB;                         \
        if (DO_E) {                                                              \
            float vs[8], vd[8];                                                  \
            _Pragma("unroll") for (int j = 0; j < 8; j++) {                      \
                vs[j] = smB[j] + 2.f*smA[j] + smc[j];                            \
                vd[j] = smc[j] - smB[j];                                         \
            }                                                                    \
            float vsm1 = __shfl_up_sync(0xffffffffu, vs[7], 1);                  \
            float vsp8 = __shfl_down_sync(0xffffffffu, vs[0], 1);                \
            float vdm1 = __shfl_up_sync(0xffffffffu, vd[7], 1);                  \
            float vdp8 = __shfl_down_sync(0xffffffffu, vd[0], 1);                \
            float ec[8];                                                         \
            {                                                                    \
                float gx, gy;                                                    \
                gx = vs[1] - vsm1; gy = vdm1 + 2.f*vd[0] + vd[1];                \
                ec[0] = fsqrt_fast(gx*gx + gy*gy);                               \
                _Pragma("unroll") for (int j = 1; j < 7; j++) {                  \
                    gx = vs[j+1] - vs[j-1];                                      \
                    gy = vd[j-1] + 2.f*vd[j] + vd[j+1];                          \
                    ec[j] = fsqrt_fast(gx*gx + gy*gy);                           \
                }                                                                \
                gx = vsp8 - vs[6]; gy = vd[6] + 2.f*vd[7] + vdp8;                \
                ec[7] = fsqrt_fast(gx*gx + gy*gy);                               \
            }                                                                    \
            float el = __shfl_up_sync(0xffffffffu, ec[7], 1);                    \
            float er = __shfl_down_sync(0xffffffffu, ec[0], 1);                  \
            float mc[8];                                                         \
            mc[0] = fmaxf(fmaxf(el, ec[0]), ec[1]);                              \
            _Pragma("unroll") for (int j = 1; j < 7; j++)                        \
                mc[j] = fmaxf(fmaxf(ec[j-1], ec[j]), ec[j+1]);                   \
            mc[7] = fmaxf(fmaxf(ec[6], ec[7]), er);                              \
            if (DO_ST) {                                                         \
                const int yo_ = y_ - 3;                                          \
                float r[8];                                                      \
                if ((yo_ > 0) && (yo_ < H - 1)) {   /* warp-uniform branch */    \
                    _Pragma("unroll") for (int j = 0; j < 8; j++) {              \
                        float nm = fmaxf(fmaxf(mRB[j], mRA[j]), mc[j])           \
                                   + colmsk[j];                                  \
                        r[j] = (eA[j] < nm) ? 0.f : eA[j];                       \
                    }                                                            \
                } else {                                                         \
                    _Pragma("unroll") for (int j = 0; j < 8; j++)                \
                        r[j] = eA[j];                                            \
                }                                                                \
                if (storerA)                                                     \
                    *reinterpret_cast<float4*>(op + (size_t)yo_ * W + c0) =      \
                        make_float4(r[0], r[1], r[2], r[3]);                     \
                if (storerB)                                                     \
                    *reinterpret_cast<float4*>(op + (size_t)yo_ * W + c0 + 4) =  \
                        make_float4(r[4], r[5], r[6], r[7]);                     \
            }                                                                    \
            _Pragma("unroll") for (int j = 0; j < 8; j++) {                      \
                eA[j] = ec[j]; mRB[j] = mRA[j]; mRA[j] = mc[j];                  \
            }                                                                    \
        }                                                                        \
        _Pragma("unroll") for (int j = 0; j < 8; j++) {                          \
            smB[j] = smA[j]; smA[j] = smc[j];                                    \
        }                                                                        \
    }                                                                            \
    _Pragma("unroll") for (int j = 0; j < 8; j++) {                              \
        hB[j] = hA[j]; hA[j] = hc[j];                                            \
    }                                                                            \
} while (0)

__global__ __launch_bounds__(NTHREADS, 4)
void edge_kernel(const float* __restrict__ img, float* __restrict__ out)
{
    const int lane = threadIdx.x & 31;
    const int warp = threadIdx.x >> 5;
    const int job  = blockIdx.x * WARPS_PER_BLOCK + warp;

    const int strip = job % NSTRIPS;
    const int t     = job / NSTRIPS;
    const int rowt  = t % NROWT;
    const int n     = t / NROWT;

    const int cb = strip * STRIP_OUT - 4;   // loaded column base (mult of 4)
    const int c0 = cb + lane * 8;           // this lane's first column
    const int y0 = rowt * ROWT;
    const int ybase = y0 - 3;

    const float* im = img + (size_t)n * H * W;
    float*       op = out + (size_t)n * H * W;

    // per-float4-group validity (groups are 4-aligned; W % 4 == 0)
    const bool okA = (c0     >= 0) && (c0     < W);
    const bool okB = (c0 + 4 >= 0) && (c0 + 4 < W);
    const float cmulA = okA ? 0.0625f : 0.f;
    const float cmulB = okB ? 0.0625f : 0.f;

    // stores: warp outputs cols cb+4 .. cb+251
    const bool storerA = (lane > 0)  && okA;
    const bool storerB = (lane < 31) && okB;

    // 0 interior, -inf at global col borders (kills suppression there)
    float colmsk[8];
    #pragma unroll
    for (int j = 0; j < 8; j++)
        colmsk[j] = ((c0 + j > 0) && (c0 + j < W - 1)) ? 0.f : NEGINF;

    float hA[8], hB[8], smA[8], smB[8], eA[8], mRA[8], mRB[8];
    #pragma unroll
    for (int j = 0; j < 8; j++) {
        hA[j]=hB[j]=0.f; smA[j]=smB[j]=0.f; eA[j]=0.f; mRA[j]=mRB[j]=0.f;
    }

    // 2-deep row prefetch (4 independent float4 loads in flight)
    float4 nx1a = ld4(im, ybase,     c0,     okA);
    float4 nx1b = ld4(im, ybase,     c0 + 4, okB);
    float4 nx2a = ld4(im, ybase + 1, c0,     okA);
    float4 nx2b = ld4(im, ybase + 1, c0 + 4, okB);

    // ---- warmup: 8 specialized iterations (first store at iy = 6) ----
    BODY(0, false, false, false);
    BODY(1, false, false, false);
    BODY(2, true,  false, false);
    BODY(3, true,  false, false);
    BODY(4, true,  true,  false);
    BODY(5, true,  true,  false);
    BODY(6, true,  true,  true);
    BODY(7, true,  true,  true);

    // ---- steady: iy = 8 .. ROWT+5 (126 iters = 63 x 2) ----
    for (int base = 8; base < ROWT + 6; base += 2) {
        BODY(base + 0, true, true, true);
        BODY(base + 1, true, true, true);
    }
}

extern "C" void kernel_launch(void* const* d_in, const int* in_sizes, int n_in,
                              void* d_out, int out_size)
{
    const float* img = (const float*)d_in[0];
    float* out = (float*)d_out;
    edge_kernel<<<NBLOCKS, NTHREADS>>>(img, out);
}